// round 11
// baseline (speedup 1.0000x reference)
#include <cuda_runtime.h>
#include <cuda_bf16.h>
#include <cstdint>

// ---------------------------------------------------------------------------
// GNN: 2-layer GraphSAGE (mean aggr) + global mean pool.
// GEMMs on the tensor pipe via mma.sync.m16n8k16 bf16 (HMMA), split-bf16
// 3-term decomposition (AhBh + AhBl + AlBh), operands as {hi,lo} bf16 pairs.
// GEMM + aggregation kernels are byte-identical to the 307us round-10 build
// (ROWU=40 conflict-free smem). This round: launch hygiene only —
// 14 -> 10 launches via zero-invariants, single-block scan, merged cvt.
// ---------------------------------------------------------------------------

#define MAXN 100000
#define MAXE 600000
#define NG   64
#define DD   128

// Scratch (device globals -- no runtime allocation allowed)
__device__ uint32_t g_xp  [MAXN * DD];   // x as pairs
__device__ uint32_t g_aggp[MAXN * DD];   // aggregation output as pairs
__device__ uint32_t g_h1p [MAXN * DD];   // h1 (post-relu) as pairs
__device__ float    g_h2  [MAXN * DD];   // h2 fp32 (for pooling)
__device__ uint32_t g_wt1 [128 * 256];   // [n][k] pairs of stacked [W1l;W1r]
__device__ uint32_t g_wt2 [128 * 256];
__device__ int      g_cnt[MAXN];         // invariant: all-zero at entry
__device__ int      g_rowptr[MAXN + 1];
__device__ int      g_cursor[MAXN];
__device__ int      g_col[MAXE];
__device__ float    g_gsum[NG * DD];     // invariant: all-zero at entry
__device__ float    g_gcnt[NG];          // invariant: all-zero at entry

// ------------------------------------------------------------- bf16 pair ops
__device__ __forceinline__ uint32_t f2pair(float f) {
    __nv_bfloat16 h = __float2bfloat16(f);
    float hf = __bfloat162float(h);
    __nv_bfloat16 l = __float2bfloat16(f - hf);
    return (uint32_t)__bfloat16_as_ushort(h) |
           ((uint32_t)__bfloat16_as_ushort(l) << 16);
}
__device__ __forceinline__ float pair2f(uint32_t p) {
    float h = __uint_as_float(p << 16);
    float l = __uint_as_float(p & 0xffff0000u);
    return h + l;
}
__device__ __forceinline__ uint32_t prmt(uint32_t a, uint32_t b, uint32_t s) {
    uint32_t r;
    asm("prmt.b32 %0,%1,%2,%3;" : "=r"(r) : "r"(a), "r"(b), "r"(s));
    return r;
}

// --------------------------------------------------------------- PTX helpers
__device__ __forceinline__ uint32_t smem_u32(const void* p) {
    uint32_t a;
    asm("{ .reg .u64 t; cvta.to.shared.u64 t, %1; cvt.u32.u64 %0, t; }"
        : "=r"(a) : "l"(p));
    return a;
}
__device__ __forceinline__ void cpasync16(uint32_t smem, const void* gmem, int sz) {
    asm volatile("cp.async.ca.shared.global [%0], [%1], 16, %2;"
                 :: "r"(smem), "l"(gmem), "r"(sz));
}
__device__ __forceinline__ void cp_commit() {
    asm volatile("cp.async.commit_group;");
}
__device__ __forceinline__ void cp_wait1() {
    asm volatile("cp.async.wait_group 1;");
}
__device__ __forceinline__ void cp_wait0() {
    asm volatile("cp.async.wait_group 0;");
}

// mma.sync m16n8k16, bf16 x bf16 -> f32, accumulate in place
__device__ __forceinline__ void mma_bf16(float (&c)[4],
                                         uint32_t a0, uint32_t a1,
                                         uint32_t a2, uint32_t a3,
                                         uint32_t b0, uint32_t b1) {
    asm volatile(
        "mma.sync.aligned.m16n8k16.row.col.f32.bf16.bf16.f32 "
        "{%0,%1,%2,%3}, {%4,%5,%6,%7}, {%8,%9}, {%0,%1,%2,%3};"
        : "+f"(c[0]), "+f"(c[1]), "+f"(c[2]), "+f"(c[3])
        : "r"(a0), "r"(a1), "r"(a2), "r"(a3), "r"(b0), "r"(b1));
}

// ------------------------------------------------------------- degree counts
__global__ void k_count(const int* __restrict__ dst, int e) {
    int i = blockIdx.x * blockDim.x + threadIdx.x;
    if (i < e) atomicAdd(&g_cnt[dst[i]], 1);
}

// ------------------------------------- single-block exclusive scan -> rowptr
__global__ void k_scan_all(int n, int e) {
    __shared__ int s[1024];
    int t = threadIdx.x;
    int CH = (n + 1023) >> 10;
    int b0 = t * CH; if (b0 > n) b0 = n;
    int b1 = b0 + CH; if (b1 > n) b1 = n;
    int sum = 0;
    for (int i = b0; i < b1; i++) sum += g_cnt[i];
    s[t] = sum;
    __syncthreads();
    #pragma unroll
    for (int off = 1; off < 1024; off <<= 1) {
        int u = (t >= off) ? s[t - off] : 0;
        __syncthreads();
        s[t] += u;
        __syncthreads();
    }
    int run = s[t] - sum;   // exclusive prefix at b0
    for (int i = b0; i < b1; i++) {
        int c = g_cnt[i];
        g_rowptr[i] = run;
        g_cursor[i] = run;
        run += c;
    }
    if (t == 0) g_rowptr[n] = e;
}

// ------------------------- CSR bucket fill (+ restore g_cnt zero-invariant)
__global__ void k_fill(const int* __restrict__ src, const int* __restrict__ dst,
                       int e, int n) {
    int i = blockIdx.x * blockDim.x + threadIdx.x;
    if (i < e) {
        int d = dst[i];
        int p = atomicAdd(&g_cursor[d], 1);
        g_col[p] = src[i];
    }
    if (i < n) g_cnt[i] = 0;
}

// -------------------- one-time conversions: x -> pairs, weights -> pairs
__global__ void k_cvtall(const float2* __restrict__ x2,
                         const float* __restrict__ W1l, const float* __restrict__ W1r,
                         const float* __restrict__ W2l, const float* __restrict__ W2r,
                         int n) {
    int i = blockIdx.x * blockDim.x + threadIdx.x;
    int nx = n * 64;
    if (i < nx) {
        float2 v = x2[i];
        uint2 o;
        o.x = f2pair(v.x);
        o.y = f2pair(v.y);
        *(uint2*)&g_xp[2 * i] = o;
    } else {
        int j = i - nx;
        if (j >= 2 * 128 * 256) return;
        int which = j >> 15;
        int idx = j & 32767;
        int nn = idx >> 8;       // output col 0..127
        int k  = idx & 255;      // stacked K 0..255
        float v;
        if (which == 0) v = (k < 128) ? W1l[k * 128 + nn] : W1r[(k - 128) * 128 + nn];
        else            v = (k < 128) ? W2l[k * 128 + nn] : W2r[(k - 128) * 128 + nn];
        uint32_t* wt = which ? g_wt2 : g_wt1;
        wt[nn * 256 + k] = f2pair(v);
    }
}

// -------------------------------------- mean aggregation, fp32 input (layer 1)
__global__ void k_agg_f(const float4* __restrict__ xin, uint32_t* __restrict__ outp, int n) {
    int gt = blockIdx.x * blockDim.x + threadIdx.x;
    int node = gt >> 5;
    int lane = gt & 31;
    if (node >= n) return;
    int beg = g_rowptr[node];
    int end = g_rowptr[node + 1];
    float4 acc = make_float4(0.f, 0.f, 0.f, 0.f);
    for (int e = beg; e < end; e++) {
        int j = g_col[e];
        float4 v = __ldg(&xin[j * 32 + lane]);
        acc.x += v.x; acc.y += v.y; acc.z += v.z; acc.w += v.w;
    }
    int deg = end - beg;
    float s = 1.0f / (float)(deg > 0 ? deg : 1);
    uint4 o;
    o.x = f2pair(acc.x * s); o.y = f2pair(acc.y * s);
    o.z = f2pair(acc.z * s); o.w = f2pair(acc.w * s);
    *(uint4*)&outp[node * 128 + lane * 4] = o;
}

// -------------------------------------- mean aggregation, pair input (layer 2)
__global__ void k_agg_p(const uint4* __restrict__ inp, uint32_t* __restrict__ outp, int n) {
    int gt = blockIdx.x * blockDim.x + threadIdx.x;
    int node = gt >> 5;
    int lane = gt & 31;
    if (node >= n) return;
    int beg = g_rowptr[node];
    int end = g_rowptr[node + 1];
    float4 acc = make_float4(0.f, 0.f, 0.f, 0.f);
    for (int e = beg; e < end; e++) {
        int j = g_col[e];
        uint4 v = __ldg(&inp[j * 32 + lane]);
        acc.x += pair2f(v.x); acc.y += pair2f(v.y);
        acc.z += pair2f(v.z); acc.w += pair2f(v.w);
    }
    int deg = end - beg;
    float s = 1.0f / (float)(deg > 0 ? deg : 1);
    uint4 o;
    o.x = f2pair(acc.x * s); o.y = f2pair(acc.y * s);
    o.z = f2pair(acc.z * s); o.w = f2pair(acc.w * s);
    *(uint4*)&outp[node * 128 + lane * 4] = o;
}

// ------------------------------------------------- split-bf16 HMMA dual GEMM
// C[M=128/blk, N=128] = [A0 | A1](K=256 pairs) @ Bw^T + bias
// 3 MMA terms: AhBh + AhBl + AlBh. K chunks of 32 pairs, cp.async 2-stage.
// smem tile rows padded to 40 uint32 (160B): g-groups land at word offsets
// {0,8,16,24} mod 32 -> all main-loop LDS.64 conflict-free.
#define ROWU 40                       // uint32 per smem row
#define STAGE_BYTES (2 * 128 * ROWU * 4)   // A tile + B tile per stage

template <bool RELU, bool PAIR_OUT>
__global__ void __launch_bounds__(256, 2)
k_gemm_mma(const uint32_t* __restrict__ A0, const uint32_t* __restrict__ A1,
           const uint32_t* __restrict__ Bw, const float* __restrict__ bias,
           void* __restrict__ Cout, int n) {
    extern __shared__ __align__(16) unsigned char smraw[];
    uint32_t sbase = smem_u32(smraw);

    int tid = threadIdx.x;
    int wid = tid >> 5;
    int lid = tid & 31;
    int g = lid >> 2;                 // group 0..7
    int t = lid & 3;                  // thread-in-group
    int rowBase = blockIdx.x * 128;
    int rowWarp = (wid >> 1) * 32;    // warp tile: 32 rows x 64 cols
    int colWarp = (wid & 1) * 64;

    float acc[2][8][4];
    #pragma unroll
    for (int rt = 0; rt < 2; rt++)
        #pragma unroll
        for (int ct = 0; ct < 8; ct++)
            #pragma unroll
            for (int q = 0; q < 4; q++) acc[rt][ct][q] = 0.0f;

    // ---- chunk loader (k-chunk c -> stage st) -------------------------------
    auto load_chunk = [&](int c, int st) {
        const uint32_t* Asrc = (c < 4) ? A0 : A1;
        int ko = (c & 3) * 32;            // pair offset within source
        int kb = c * 32;                  // pair offset within stacked K
        uint32_t sA = sbase + st * STAGE_BYTES;
        uint32_t sB = sA + 128 * ROWU * 4;
        #pragma unroll
        for (int j = 0; j < 4; j++) {     // A: 128 rows x 32 pairs = 1024 x16B
            int idx = tid + j * 256;
            int r = idx >> 3, seg = idx & 7;
            int gr = rowBase + r;
            int sz = (gr < n) ? 16 : 0;
            int grc = (gr < n) ? gr : (n - 1);
            cpasync16(sA + r * (ROWU * 4) + seg * 16,
                      Asrc + (size_t)grc * 128 + ko + seg * 4, sz);
        }
        #pragma unroll
        for (int j = 0; j < 4; j++) {     // B: 128 n-rows x 32 pairs
            int idx = tid + j * 256;
            int r = idx >> 3, seg = idx & 7;
            cpasync16(sB + r * (ROWU * 4) + seg * 16,
                      Bw + r * 256 + kb + seg * 4, 16);
        }
        cp_commit();
    };

    load_chunk(0, 0);

    for (int c = 0; c < 8; c++) {
        if (c < 7) { load_chunk(c + 1, (c + 1) & 1); cp_wait1(); }
        else       { cp_wait0(); }
        __syncthreads();

        const uint32_t* sA = (const uint32_t*)(smraw + (c & 1) * STAGE_BYTES);
        const uint32_t* sB = sA + 128 * ROWU;

        #pragma unroll
        for (int kk = 0; kk < 32; kk += 16) {
            uint32_t Ah[2][4], Al[2][4];
            #pragma unroll
            for (int rt = 0; rt < 2; rt++) {
                const uint32_t* p0 = sA + (rowWarp + rt * 16 + g) * ROWU + kk + 2 * t;
                const uint32_t* p1 = p0 + 8 * ROWU;
                uint2 q;
                q = *(const uint2*)p0;
                Ah[rt][0] = prmt(q.x, q.y, 0x5410); Al[rt][0] = prmt(q.x, q.y, 0x7632);
                q = *(const uint2*)p1;
                Ah[rt][1] = prmt(q.x, q.y, 0x5410); Al[rt][1] = prmt(q.x, q.y, 0x7632);
                q = *(const uint2*)(p0 + 8);
                Ah[rt][2] = prmt(q.x, q.y, 0x5410); Al[rt][2] = prmt(q.x, q.y, 0x7632);
                q = *(const uint2*)(p1 + 8);
                Ah[rt][3] = prmt(q.x, q.y, 0x5410); Al[rt][3] = prmt(q.x, q.y, 0x7632);
            }
            #pragma unroll
            for (int ct = 0; ct < 8; ct++) {
                const uint32_t* pb = sB + (colWarp + ct * 8 + g) * ROWU + kk + 2 * t;
                uint2 q0 = *(const uint2*)pb;
                uint2 q1 = *(const uint2*)(pb + 8);
                uint32_t Bh0 = prmt(q0.x, q0.y, 0x5410), Bl0 = prmt(q0.x, q0.y, 0x7632);
                uint32_t Bh1 = prmt(q1.x, q1.y, 0x5410), Bl1 = prmt(q1.x, q1.y, 0x7632);
                #pragma unroll
                for (int rt = 0; rt < 2; rt++) {
                    mma_bf16(acc[rt][ct], Ah[rt][0], Ah[rt][1], Ah[rt][2], Ah[rt][3], Bh0, Bh1);
                    mma_bf16(acc[rt][ct], Ah[rt][0], Ah[rt][1], Ah[rt][2], Ah[rt][3], Bl0, Bl1);
                    mma_bf16(acc[rt][ct], Al[rt][0], Al[rt][1], Al[rt][2], Al[rt][3], Bh0, Bh1);
                }
            }
        }
        __syncthreads();
    }

    // ---- epilogue: bias (+relu), direct stores (32B-sector aligned) ---------
    float bc0[8], bc1[8];
    #pragma unroll
    for (int ct = 0; ct < 8; ct++) {
        int col = colWarp + ct * 8 + 2 * t;
        bc0[ct] = __ldg(&bias[col]);
        bc1[ct] = __ldg(&bias[col + 1]);
    }
    #pragma unroll
    for (int rt = 0; rt < 2; rt++) {
        #pragma unroll
        for (int half = 0; half < 2; half++) {
            int grow = rowBase + rowWarp + rt * 16 + half * 8 + g;
            if (grow >= n) continue;
            #pragma unroll
            for (int ct = 0; ct < 8; ct++) {
                int col = colWarp + ct * 8 + 2 * t;
                float v0 = acc[rt][ct][half * 2 + 0] + bc0[ct];
                float v1 = acc[rt][ct][half * 2 + 1] + bc1[ct];
                if (RELU) { v0 = fmaxf(v0, 0.f); v1 = fmaxf(v1, 0.f); }
                if (PAIR_OUT) {
                    uint2 o; o.x = f2pair(v0); o.y = f2pair(v1);
                    *(uint2*)&((uint32_t*)Cout)[(size_t)grow * 128 + col] = o;
                } else {
                    float2 o; o.x = v0; o.y = v1;
                    *(float2*)&((float*)Cout)[(size_t)grow * 128 + col] = o;
                }
            }
        }
    }
}

// --------------------------------------------- pooled segment sums (batch sorted)
__global__ void k_pool(const float* __restrict__ h2, const int* __restrict__ batch, int n) {
    const int ROWS = 256;
    int tx = threadIdx.x;           // 128 threads: one per feature column
    int r0 = blockIdx.x * ROWS;
    if (r0 >= n) return;
    int rend = r0 + ROWS; if (rend > n) rend = n;
    float acc = 0.0f;
    int cur = batch[r0];
    int cl = 0;
    for (int r = r0; r < rend; r++) {
        int g = batch[r];
        if (g != cur) {
            atomicAdd(&g_gsum[cur * DD + tx], acc);
            if (tx == 0) atomicAdd(&g_gcnt[cur], (float)cl);
            acc = 0.0f; cl = 0; cur = g;
        }
        acc += h2[r * 128 + tx];
        cl++;
    }
    atomicAdd(&g_gsum[cur * DD + tx], acc);
    if (tx == 0) atomicAdd(&g_gcnt[cur], (float)cl);
}

// -------------- final output (single block; restores zero-invariants)
__global__ void k_final(float* __restrict__ out) {
    __shared__ float sc[NG];
    int t = threadIdx.x;
    if (t < NG) sc[t] = g_gcnt[t];
    __syncthreads();
    for (int i = t; i < NG * DD; i += 1024) {
        out[i] = g_gsum[i] / fmaxf(sc[i >> 7], 1.0f);
        g_gsum[i] = 0.0f;
    }
    if (t < NG) g_gcnt[t] = 0.0f;
}

// ---------------------------------------------------------------------------
extern "C" void kernel_launch(void* const* d_in, const int* in_sizes, int n_in,
                              void* d_out, int out_size) {
    (void)n_in; (void)out_size;
    const float* x     = (const float*)d_in[0];
    const int*   ei    = (const int*)  d_in[1];
    const int*   batch = (const int*)  d_in[2];
    const float* W1l   = (const float*)d_in[3];
    const float* b1    = (const float*)d_in[4];
    const float* W1r   = (const float*)d_in[5];
    const float* W2l   = (const float*)d_in[6];
    const float* b2    = (const float*)d_in[7];
    const float* W2r   = (const float*)d_in[8];
    float*       out   = (float*)d_out;

    int n = in_sizes[0] / 128;   // nodes
    int e = in_sizes[1] / 2;     // edges
    const int* src = ei;         // edge_index[0]
    const int* dst = ei + e;     // edge_index[1]

    void *p_xp, *p_aggp, *p_h1p, *p_h2, *p_wt1, *p_wt2;
    cudaGetSymbolAddress(&p_xp,   g_xp);
    cudaGetSymbolAddress(&p_aggp, g_aggp);
    cudaGetSymbolAddress(&p_h1p,  g_h1p);
    cudaGetSymbolAddress(&p_h2,   g_h2);
    cudaGetSymbolAddress(&p_wt1,  g_wt1);
    cudaGetSymbolAddress(&p_wt2,  g_wt2);
    uint32_t* xp   = (uint32_t*)p_xp;
    uint32_t* aggp = (uint32_t*)p_aggp;
    uint32_t* h1p  = (uint32_t*)p_h1p;
    float*    h2   = (float*)p_h2;
    uint32_t* wt1  = (uint32_t*)p_wt1;
    uint32_t* wt2  = (uint32_t*)p_wt2;

    const int GEMM_SMEM = 2 * STAGE_BYTES;   // 81920
    cudaFuncSetAttribute(k_gemm_mma<true, true>,
                         cudaFuncAttributeMaxDynamicSharedMemorySize, GEMM_SMEM);
    cudaFuncSetAttribute(k_gemm_mma<false, false>,
                         cudaFuncAttributeMaxDynamicSharedMemorySize, GEMM_SMEM);

    // CSR build (g_cnt arrives zeroed; k_fill restores the invariant)
    k_count   <<<(e + 255) / 256, 256>>>(dst, e);
    k_scan_all<<<1, 1024>>>(n, e);
    k_fill    <<<(e + 255) / 256, 256>>>(src, dst, e, n);

    // One-time conversions: x -> pairs, weights -> [n][k] pairs (merged)
    int cvtTot = n * 64 + 2 * 128 * 256;
    k_cvtall<<<(cvtTot + 255) / 256, 256>>>((const float2*)x, W1l, W1r, W2l, W2r, n);

    int aggBlocks  = (n * 32 + 255) / 256;
    int gemmBlocks = (n + 127) / 128;

    // Layer 1: agg = mean(x[nbr]); h1 = relu([agg,x]@[W1l;W1r] + b1)
    k_agg_f<<<aggBlocks, 256>>>((const float4*)x, aggp, n);
    k_gemm_mma<true, true><<<gemmBlocks, 256, GEMM_SMEM>>>(aggp, xp, wt1, b1, h1p, n);

    // Layer 2: agg = mean(h1[nbr]); h2 = [agg,h1]@[W2l;W2r] + b2
    k_agg_p<<<aggBlocks, 256>>>((const uint4*)h1p, aggp, n);
    k_gemm_mma<false, false><<<gemmBlocks, 256, GEMM_SMEM>>>(aggp, h1p, wt2, b2, h2, n);

    // Global mean pool (g_gsum/g_gcnt arrive zeroed; k_final restores)
    k_pool <<<(n + 255) / 256, 128>>>(h2, batch, n);
    k_final<<<1, 1024>>>(out);
}

// round 12
// speedup vs baseline: 1.8273x; 1.8273x over previous
#include <cuda_runtime.h>
#include <cuda_bf16.h>
#include <cstdint>

// ---------------------------------------------------------------------------
// GNN: 2-layer GraphSAGE (mean aggr) + global mean pool.
// GEMMs on the tensor pipe via mma.sync.m16n8k16 bf16 (HMMA), split-bf16
// 3-term decomposition (AhBh+AhBl+AlBh), operands as {hi,lo} bf16 pairs.
// Baseline == round-10 (307us, ROWU=40 conflict-free smem, multi-block
// coalesced scan). ONE change this round: global mean pool is fused into
// GEMM2's epilogue (tile -> smem -> per-block segment sums -> few atomics),
// eliminating the h2 global round-trip and the k_pool launch.
// ---------------------------------------------------------------------------

#define MAXN 100000
#define MAXE 600000
#define NG   64
#define DD   128

// Scratch (device globals -- no runtime allocation allowed)
__device__ uint32_t g_xp  [MAXN * DD];   // x as pairs
__device__ uint32_t g_aggp[MAXN * DD];   // aggregation output as pairs
__device__ uint32_t g_h1p [MAXN * DD];   // h1 (post-relu) as pairs
__device__ uint32_t g_wt1 [128 * 256];   // [n][k] pairs of stacked [W1l;W1r]
__device__ uint32_t g_wt2 [128 * 256];
__device__ int      g_cnt[MAXN];
__device__ int      g_rowptr[MAXN + 1];
__device__ int      g_cursor[MAXN];
__device__ int      g_col[MAXE];
__device__ float    g_gsum[NG * DD];
__device__ float    g_gcnt[NG];
__device__ int      g_bsums[1024];

// ------------------------------------------------------------- bf16 pair ops
__device__ __forceinline__ uint32_t f2pair(float f) {
    __nv_bfloat16 h = __float2bfloat16(f);
    float hf = __bfloat162float(h);
    __nv_bfloat16 l = __float2bfloat16(f - hf);
    return (uint32_t)__bfloat16_as_ushort(h) |
           ((uint32_t)__bfloat16_as_ushort(l) << 16);
}
__device__ __forceinline__ float pair2f(uint32_t p) {
    float h = __uint_as_float(p << 16);
    float l = __uint_as_float(p & 0xffff0000u);
    return h + l;
}
__device__ __forceinline__ uint32_t prmt(uint32_t a, uint32_t b, uint32_t s) {
    uint32_t r;
    asm("prmt.b32 %0,%1,%2,%3;" : "=r"(r) : "r"(a), "r"(b), "r"(s));
    return r;
}

// --------------------------------------------------------------- PTX helpers
__device__ __forceinline__ uint32_t smem_u32(const void* p) {
    uint32_t a;
    asm("{ .reg .u64 t; cvta.to.shared.u64 t, %1; cvt.u32.u64 %0, t; }"
        : "=r"(a) : "l"(p));
    return a;
}
__device__ __forceinline__ void cpasync16(uint32_t smem, const void* gmem, int sz) {
    asm volatile("cp.async.ca.shared.global [%0], [%1], 16, %2;"
                 :: "r"(smem), "l"(gmem), "r"(sz));
}
__device__ __forceinline__ void cp_commit() {
    asm volatile("cp.async.commit_group;");
}
__device__ __forceinline__ void cp_wait1() {
    asm volatile("cp.async.wait_group 1;");
}
__device__ __forceinline__ void cp_wait0() {
    asm volatile("cp.async.wait_group 0;");
}

// mma.sync m16n8k16, bf16 x bf16 -> f32, accumulate in place
__device__ __forceinline__ void mma_bf16(float (&c)[4],
                                         uint32_t a0, uint32_t a1,
                                         uint32_t a2, uint32_t a3,
                                         uint32_t b0, uint32_t b1) {
    asm volatile(
        "mma.sync.aligned.m16n8k16.row.col.f32.bf16.bf16.f32 "
        "{%0,%1,%2,%3}, {%4,%5,%6,%7}, {%8,%9}, {%0,%1,%2,%3};"
        : "+f"(c[0]), "+f"(c[1]), "+f"(c[2]), "+f"(c[3])
        : "r"(a0), "r"(a1), "r"(a2), "r"(a3), "r"(b0), "r"(b1));
}

// ---------------------------------------------------------------- init zeros
__global__ void k_init(int n) {
    int i = blockIdx.x * blockDim.x + threadIdx.x;
    if (i < n)       g_cnt[i] = 0;
    if (i < NG * DD) g_gsum[i] = 0.0f;
    if (i < NG)      g_gcnt[i] = 0.0f;
}

// ------------------------------------------------------------- degree counts
__global__ void k_count(const int* __restrict__ dst, int e) {
    int i = blockIdx.x * blockDim.x + threadIdx.x;
    if (i < e) atomicAdd(&g_cnt[dst[i]], 1);
}

// ----------------------------------------------------- 2-level exclusive scan
__global__ void k_scan1(int n) {
    __shared__ int s[1024];
    int t = threadIdx.x;
    int i = blockIdx.x * 1024 + t;
    int v = (i < n) ? g_cnt[i] : 0;
    s[t] = v;
    __syncthreads();
    #pragma unroll
    for (int off = 1; off < 1024; off <<= 1) {
        int u = (t >= off) ? s[t - off] : 0;
        __syncthreads();
        s[t] += u;
        __syncthreads();
    }
    if (i < n) g_rowptr[i] = s[t];              // inclusive within block
    if (t == 1023) g_bsums[blockIdx.x] = s[1023];
}

__global__ void k_scan2(int nb) {               // block scan over block sums
    __shared__ int s[1024];
    int t = threadIdx.x;
    int v = (t < nb) ? g_bsums[t] : 0;
    s[t] = v;
    __syncthreads();
    #pragma unroll
    for (int off = 1; off < 1024; off <<= 1) {
        int u = (t >= off) ? s[t - off] : 0;
        __syncthreads();
        s[t] += u;
        __syncthreads();
    }
    if (t < nb) g_bsums[t] = s[t] - v;          // exclusive
}

__global__ void k_scan3(int n, int e) {
    int i = blockIdx.x * blockDim.x + threadIdx.x;
    if (i < n) {
        int ex = g_bsums[i >> 10] + g_rowptr[i] - g_cnt[i];
        g_rowptr[i] = ex;
        g_cursor[i] = ex;
    }
    if (i == 0) g_rowptr[n] = e;
}

// ----------------------------------------------------------- CSR bucket fill
__global__ void k_fill(const int* __restrict__ src, const int* __restrict__ dst, int e) {
    int i = blockIdx.x * blockDim.x + threadIdx.x;
    if (i < e) {
        int d = dst[i];
        int p = atomicAdd(&g_cursor[d], 1);
        g_col[p] = src[i];
    }
}

// ---------------------------------------------------------- fp32 -> pair cvt
__global__ void k_cvt(const float4* __restrict__ x, uint32_t* __restrict__ xp, int tot4) {
    int i = blockIdx.x * blockDim.x + threadIdx.x;
    if (i < tot4) {
        float4 v = x[i];
        uint4 o;
        o.x = f2pair(v.x); o.y = f2pair(v.y); o.z = f2pair(v.z); o.w = f2pair(v.w);
        *(uint4*)&xp[i * 4] = o;
    }
}

// ------------------------------------------- weights -> [n][k] pair array
__global__ void k_cvtw(const float* __restrict__ W1l, const float* __restrict__ W1r,
                       const float* __restrict__ W2l, const float* __restrict__ W2r) {
    int i = blockIdx.x * blockDim.x + threadIdx.x;   // 2 * 128 * 256
    if (i >= 2 * 128 * 256) return;
    int which = i >> 15;
    int idx = i & 32767;
    int nn = idx >> 8;       // output col 0..127
    int k  = idx & 255;      // stacked K 0..255
    float v;
    if (which == 0) v = (k < 128) ? W1l[k * 128 + nn] : W1r[(k - 128) * 128 + nn];
    else            v = (k < 128) ? W2l[k * 128 + nn] : W2r[(k - 128) * 128 + nn];
    uint32_t* wt = which ? g_wt2 : g_wt1;
    wt[nn * 256 + k] = f2pair(v);
}

// -------------------------------------- mean aggregation, fp32 input (layer 1)
__global__ void k_agg_f(const float4* __restrict__ xin, uint32_t* __restrict__ outp, int n) {
    int gt = blockIdx.x * blockDim.x + threadIdx.x;
    int node = gt >> 5;
    int lane = gt & 31;
    if (node >= n) return;
    int beg = g_rowptr[node];
    int end = g_rowptr[node + 1];
    float4 acc = make_float4(0.f, 0.f, 0.f, 0.f);
    for (int e = beg; e < end; e++) {
        int j = g_col[e];
        float4 v = __ldg(&xin[j * 32 + lane]);
        acc.x += v.x; acc.y += v.y; acc.z += v.z; acc.w += v.w;
    }
    int deg = end - beg;
    float s = 1.0f / (float)(deg > 0 ? deg : 1);
    uint4 o;
    o.x = f2pair(acc.x * s); o.y = f2pair(acc.y * s);
    o.z = f2pair(acc.z * s); o.w = f2pair(acc.w * s);
    *(uint4*)&outp[node * 128 + lane * 4] = o;
}

// -------------------------------------- mean aggregation, pair input (layer 2)
__global__ void k_agg_p(const uint4* __restrict__ inp, uint32_t* __restrict__ outp, int n) {
    int gt = blockIdx.x * blockDim.x + threadIdx.x;
    int node = gt >> 5;
    int lane = gt & 31;
    if (node >= n) return;
    int beg = g_rowptr[node];
    int end = g_rowptr[node + 1];
    float4 acc = make_float4(0.f, 0.f, 0.f, 0.f);
    for (int e = beg; e < end; e++) {
        int j = g_col[e];
        uint4 v = __ldg(&inp[j * 32 + lane]);
        acc.x += pair2f(v.x); acc.y += pair2f(v.y);
        acc.z += pair2f(v.z); acc.w += pair2f(v.w);
    }
    int deg = end - beg;
    float s = 1.0f / (float)(deg > 0 ? deg : 1);
    uint4 o;
    o.x = f2pair(acc.x * s); o.y = f2pair(acc.y * s);
    o.z = f2pair(acc.z * s); o.w = f2pair(acc.w * s);
    *(uint4*)&outp[node * 128 + lane * 4] = o;
}

// ------------------------------------------------- split-bf16 HMMA dual GEMM
// C[M=128/blk, N=128] = [A0 | A1](K=256 pairs) @ Bw^T + bias
// 3 MMA terms: AhBh + AhBl + AlBh. K chunks of 32 pairs, cp.async 2-stage.
// smem tile rows padded to 40 uint32 (160B): conflict-free main-loop LDS.64.
// POOL epilogue (GEMM2): tile -> smem, per-block segment sums by sorted batch,
// few atomics to g_gsum/g_gcnt. No h2 global round-trip, no k_pool kernel.
#define ROWU 40                            // uint32 per smem row
#define STAGE_BYTES (2 * 128 * ROWU * 4)   // A tile + B tile per stage (40960)
#define TILE_STRIDE 132                    // fp32 pool-tile row stride

template <bool RELU, bool PAIR_OUT, bool POOL>
__global__ void __launch_bounds__(256, 2)
k_gemm_mma(const uint32_t* __restrict__ A0, const uint32_t* __restrict__ A1,
           const uint32_t* __restrict__ Bw, const float* __restrict__ bias,
           void* __restrict__ Cout, const int* __restrict__ batch, int n) {
    extern __shared__ __align__(16) unsigned char smraw[];
    uint32_t sbase = smem_u32(smraw);

    int tid = threadIdx.x;
    int wid = tid >> 5;
    int lid = tid & 31;
    int g = lid >> 2;                 // group 0..7
    int t = lid & 3;                  // thread-in-group
    int rowBase = blockIdx.x * 128;
    int rowWarp = (wid >> 1) * 32;    // warp tile: 32 rows x 64 cols
    int colWarp = (wid & 1) * 64;

    float acc[2][8][4];
    #pragma unroll
    for (int rt = 0; rt < 2; rt++)
        #pragma unroll
        for (int ct = 0; ct < 8; ct++)
            #pragma unroll
            for (int q = 0; q < 4; q++) acc[rt][ct][q] = 0.0f;

    // ---- chunk loader (k-chunk c -> stage st) -------------------------------
    auto load_chunk = [&](int c, int st) {
        const uint32_t* Asrc = (c < 4) ? A0 : A1;
        int ko = (c & 3) * 32;            // pair offset within source
        int kb = c * 32;                  // pair offset within stacked K
        uint32_t sA = sbase + st * STAGE_BYTES;
        uint32_t sB = sA + 128 * ROWU * 4;
        #pragma unroll
        for (int j = 0; j < 4; j++) {     // A: 128 rows x 32 pairs = 1024 x16B
            int idx = tid + j * 256;
            int r = idx >> 3, seg = idx & 7;
            int gr = rowBase + r;
            int sz = (gr < n) ? 16 : 0;
            int grc = (gr < n) ? gr : (n - 1);
            cpasync16(sA + r * (ROWU * 4) + seg * 16,
                      Asrc + (size_t)grc * 128 + ko + seg * 4, sz);
        }
        #pragma unroll
        for (int j = 0; j < 4; j++) {     // B: 128 n-rows x 32 pairs
            int idx = tid + j * 256;
            int r = idx >> 3, seg = idx & 7;
            cpasync16(sB + r * (ROWU * 4) + seg * 16,
                      Bw + r * 256 + kb + seg * 4, 16);
        }
        cp_commit();
    };

    load_chunk(0, 0);

    for (int c = 0; c < 8; c++) {
        if (c < 7) { load_chunk(c + 1, (c + 1) & 1); cp_wait1(); }
        else       { cp_wait0(); }
        __syncthreads();

        const uint32_t* sA = (const uint32_t*)(smraw + (c & 1) * STAGE_BYTES);
        const uint32_t* sB = sA + 128 * ROWU;

        #pragma unroll
        for (int kk = 0; kk < 32; kk += 16) {
            uint32_t Ah[2][4], Al[2][4];
            #pragma unroll
            for (int rt = 0; rt < 2; rt++) {
                const uint32_t* p0 = sA + (rowWarp + rt * 16 + g) * ROWU + kk + 2 * t;
                const uint32_t* p1 = p0 + 8 * ROWU;
                uint2 q;
                q = *(const uint2*)p0;
                Ah[rt][0] = prmt(q.x, q.y, 0x5410); Al[rt][0] = prmt(q.x, q.y, 0x7632);
                q = *(const uint2*)p1;
                Ah[rt][1] = prmt(q.x, q.y, 0x5410); Al[rt][1] = prmt(q.x, q.y, 0x7632);
                q = *(const uint2*)(p0 + 8);
                Ah[rt][2] = prmt(q.x, q.y, 0x5410); Al[rt][2] = prmt(q.x, q.y, 0x7632);
                q = *(const uint2*)(p1 + 8);
                Ah[rt][3] = prmt(q.x, q.y, 0x5410); Al[rt][3] = prmt(q.x, q.y, 0x7632);
            }
            #pragma unroll
            for (int ct = 0; ct < 8; ct++) {
                const uint32_t* pb = sB + (colWarp + ct * 8 + g) * ROWU + kk + 2 * t;
                uint2 q0 = *(const uint2*)pb;
                uint2 q1 = *(const uint2*)(pb + 8);
                uint32_t Bh0 = prmt(q0.x, q0.y, 0x5410), Bl0 = prmt(q0.x, q0.y, 0x7632);
                uint32_t Bh1 = prmt(q1.x, q1.y, 0x5410), Bl1 = prmt(q1.x, q1.y, 0x7632);
                #pragma unroll
                for (int rt = 0; rt < 2; rt++) {
                    mma_bf16(acc[rt][ct], Ah[rt][0], Ah[rt][1], Ah[rt][2], Ah[rt][3], Bh0, Bh1);
                    mma_bf16(acc[rt][ct], Ah[rt][0], Ah[rt][1], Ah[rt][2], Ah[rt][3], Bl0, Bl1);
                    mma_bf16(acc[rt][ct], Al[rt][0], Al[rt][1], Al[rt][2], Al[rt][3], Bh0, Bh1);
                }
            }
        }
        __syncthreads();
    }

    // ---- epilogue -----------------------------------------------------------
    float bc0[8], bc1[8];
    #pragma unroll
    for (int ct = 0; ct < 8; ct++) {
        int col = colWarp + ct * 8 + 2 * t;
        bc0[ct] = __ldg(&bias[col]);
        bc1[ct] = __ldg(&bias[col + 1]);
    }

    if (POOL) {
        // Fused global-mean-pool: stash tile in smem (stage buffers are dead
        // after the last __syncthreads), segment-sum columns by sorted batch.
        float* tile = (float*)smraw;                          // 128 x TILE_STRIDE
        int* sbatch = (int*)(smraw + 128 * TILE_STRIDE * 4);  // 128 ids
        #pragma unroll
        for (int rt = 0; rt < 2; rt++) {
            #pragma unroll
            for (int half = 0; half < 2; half++) {
                int lrow = rowWarp + rt * 16 + half * 8 + g;
                #pragma unroll
                for (int ct = 0; ct < 8; ct++) {
                    int col = colWarp + ct * 8 + 2 * t;
                    float v0 = acc[rt][ct][half * 2 + 0] + bc0[ct];
                    float v1 = acc[rt][ct][half * 2 + 1] + bc1[ct];
                    if (RELU) { v0 = fmaxf(v0, 0.f); v1 = fmaxf(v1, 0.f); }
                    float2 o; o.x = v0; o.y = v1;
                    *(float2*)&tile[lrow * TILE_STRIDE + col] = o;
                }
            }
        }
        if (tid < 128) {
            int gr = rowBase + tid;
            sbatch[tid] = (gr < n) ? __ldg(&batch[gr]) : -1;
        }
        __syncthreads();
        if (tid < 128) {
            int col = tid;
            float pacc = 0.0f;
            int cur = sbatch[0];
            int cnt = 0;
            for (int r = 0; r < 128; r++) {
                int b = sbatch[r];
                if (b != cur) {
                    if (cur >= 0) {
                        atomicAdd(&g_gsum[cur * DD + col], pacc);
                        if (col == 0) atomicAdd(&g_gcnt[cur], (float)cnt);
                    }
                    pacc = 0.0f; cnt = 0; cur = b;
                }
                if (b >= 0) { pacc += tile[r * TILE_STRIDE + col]; cnt++; }
            }
            if (cur >= 0) {
                atomicAdd(&g_gsum[cur * DD + col], pacc);
                if (col == 0) atomicAdd(&g_gcnt[cur], (float)cnt);
            }
        }
    } else {
        #pragma unroll
        for (int rt = 0; rt < 2; rt++) {
            #pragma unroll
            for (int half = 0; half < 2; half++) {
                int grow = rowBase + rowWarp + rt * 16 + half * 8 + g;
                if (grow >= n) continue;
                #pragma unroll
                for (int ct = 0; ct < 8; ct++) {
                    int col = colWarp + ct * 8 + 2 * t;
                    float v0 = acc[rt][ct][half * 2 + 0] + bc0[ct];
                    float v1 = acc[rt][ct][half * 2 + 1] + bc1[ct];
                    if (RELU) { v0 = fmaxf(v0, 0.f); v1 = fmaxf(v1, 0.f); }
                    if (PAIR_OUT) {
                        uint2 o; o.x = f2pair(v0); o.y = f2pair(v1);
                        *(uint2*)&((uint32_t*)Cout)[(size_t)grow * 128 + col] = o;
                    } else {
                        float2 o; o.x = v0; o.y = v1;
                        *(float2*)&((float*)Cout)[(size_t)grow * 128 + col] = o;
                    }
                }
            }
        }
    }
}

// ---------------------------------------------------------------- final output
__global__ void k_final(float* __restrict__ out) {
    int i = blockIdx.x * blockDim.x + threadIdx.x;
    if (i < NG * DD) {
        float c = g_gcnt[i >> 7];
        out[i] = g_gsum[i] / fmaxf(c, 1.0f);
    }
}

// ---------------------------------------------------------------------------
extern "C" void kernel_launch(void* const* d_in, const int* in_sizes, int n_in,
                              void* d_out, int out_size) {
    (void)n_in; (void)out_size;
    const float* x     = (const float*)d_in[0];
    const int*   ei    = (const int*)  d_in[1];
    const int*   batch = (const int*)  d_in[2];
    const float* W1l   = (const float*)d_in[3];
    const float* b1    = (const float*)d_in[4];
    const float* W1r   = (const float*)d_in[5];
    const float* W2l   = (const float*)d_in[6];
    const float* b2    = (const float*)d_in[7];
    const float* W2r   = (const float*)d_in[8];
    float*       out   = (float*)d_out;

    int n = in_sizes[0] / 128;   // nodes
    int e = in_sizes[1] / 2;     // edges
    const int* src = ei;         // edge_index[0]
    const int* dst = ei + e;     // edge_index[1]

    void *p_xp, *p_aggp, *p_h1p, *p_wt1, *p_wt2;
    cudaGetSymbolAddress(&p_xp,   g_xp);
    cudaGetSymbolAddress(&p_aggp, g_aggp);
    cudaGetSymbolAddress(&p_h1p,  g_h1p);
    cudaGetSymbolAddress(&p_wt1,  g_wt1);
    cudaGetSymbolAddress(&p_wt2,  g_wt2);
    uint32_t* xp   = (uint32_t*)p_xp;
    uint32_t* aggp = (uint32_t*)p_aggp;
    uint32_t* h1p  = (uint32_t*)p_h1p;
    uint32_t* wt1  = (uint32_t*)p_wt1;
    uint32_t* wt2  = (uint32_t*)p_wt2;

    const int GEMM_SMEM = 2 * STAGE_BYTES;   // 81920 (covers pool tile 68096)
    cudaFuncSetAttribute(k_gemm_mma<true, true, false>,
                         cudaFuncAttributeMaxDynamicSharedMemorySize, GEMM_SMEM);
    cudaFuncSetAttribute(k_gemm_mma<false, false, true>,
                         cudaFuncAttributeMaxDynamicSharedMemorySize, GEMM_SMEM);

    int nb = (n + 1023) / 1024;

    // CSR build (by dst)
    k_init <<<(n + 255) / 256, 256>>>(n);
    k_count<<<(e + 255) / 256, 256>>>(dst, e);
    k_scan1<<<nb, 1024>>>(n);
    k_scan2<<<1, 1024>>>(nb);
    k_scan3<<<(n + 255) / 256, 256>>>(n, e);
    k_fill <<<(e + 255) / 256, 256>>>(src, dst, e);

    // One-time conversions: x -> pairs, weights -> [n][k] pairs
    int tot4 = n * 32;
    k_cvt <<<(tot4 + 255) / 256, 256>>>((const float4*)x, xp, tot4);
    k_cvtw<<<(2 * 128 * 256 + 255) / 256, 256>>>(W1l, W1r, W2l, W2r);

    int aggBlocks  = (n * 32 + 255) / 256;
    int gemmBlocks = (n + 127) / 128;

    // Layer 1: agg = mean(x[nbr]); h1 = relu([agg,x]@[W1l;W1r] + b1)
    k_agg_f<<<aggBlocks, 256>>>((const float4*)x, aggp, n);
    k_gemm_mma<true, true, false><<<gemmBlocks, 256, GEMM_SMEM>>>(
        aggp, xp, wt1, b1, h1p, nullptr, n);

    // Layer 2: agg = mean(h1[nbr]); h2 = [agg,h1]@[W2l;W2r] + b2, pooled inline
    k_agg_p<<<aggBlocks, 256>>>((const uint4*)h1p, aggp, n);
    k_gemm_mma<false, false, true><<<gemmBlocks, 256, GEMM_SMEM>>>(
        aggp, h1p, wt2, b2, nullptr, batch, n);

    // Global mean pool finalize
    k_final<<<(NG * DD + 255) / 256, 256>>>(out);
}